// round 1
// baseline (speedup 1.0000x reference)
#include <cuda_runtime.h>
#include <math.h>

// Problem dims (fixed by the reference setup_inputs)
#define BB 64
#define SS 1024
#define DD 512
#define NROWS (BB*SS)

// kernel-1 S-chunking
#define NCH 8
#define SCHUNK (SS/NCH)

// kernel-2 config
#define TPB 128
#define RPB 16

#define EPS_F 1e-5f
#define MAXT 45.054565f   // asinh(sqrt(fp32_max)); never binding for this data but kept exact

// scratch (no cudaMalloc allowed)
__device__ __align__(16) float g_part[BB*NCH*DD];
__device__ __align__(16) float g_c1[BB*DD];
__device__ __align__(16) float g_mean[DD];

// ---------------------------------------------------------------------------
// 512-thread block sum reduction (returns full sum to all threads)
__device__ __forceinline__ float red512(float v) {
    __shared__ float sh[16];
    int w = threadIdx.x >> 5, l = threadIdx.x & 31;
    #pragma unroll
    for (int o = 16; o > 0; o >>= 1) v += __shfl_down_sync(0xffffffffu, v, o);
    if (l == 0) sh[w] = v;
    __syncthreads();
    float r = 0.f;
    #pragma unroll
    for (int i = 0; i < 16; i++) r += sh[i];
    return r;
}

// ---------------------------------------------------------------------------
// K1a: per-(b,chunk) column partial sums over S
__global__ void k_partial(const float* __restrict__ x) {
    int bc = blockIdx.x;            // b*NCH + c
    int d  = threadIdx.x;           // 0..511
    const float* p = x + (size_t)( (bc / NCH) * SS + (bc % NCH) * SCHUNK ) * DD + d;
    float a0 = 0.f, a1 = 0.f, a2 = 0.f, a3 = 0.f;
    #pragma unroll 4
    for (int s = 0; s < SCHUNK; s += 4) {
        a0 += p[(size_t)(s + 0) * DD];
        a1 += p[(size_t)(s + 1) * DD];
        a2 += p[(size_t)(s + 2) * DD];
        a3 += p[(size_t)(s + 3) * DD];
    }
    g_part[(size_t)bc * DD + d] = (a0 + a1) + (a2 + a3);
}

// K1b: per-b centroid normalization -> c1[b][d]
__global__ void k_c1() {
    int b = blockIdx.x, d = threadIdx.x;
    float a = 0.f;
    #pragma unroll
    for (int c = 0; c < NCH; c++) a += g_part[(size_t)(b * NCH + c) * DD + d];
    a *= (1.f / SS);
    float t = (d == 0) ? -a * a : a * a;     // Lorentz <avg,avg>
    float lin = red512(t);
    float denom = sqrtf(fmaxf(-lin, 1e-8f));
    g_c1[(size_t)b * DD + d] = a / denom;
}

// K1c: centroid over B -> mean[d]
__global__ void k_mean() {
    int d = threadIdx.x;
    float a = 0.f;
    #pragma unroll 8
    for (int b = 0; b < BB; b++) a += g_c1[(size_t)b * DD + d];
    a *= (1.f / BB);
    float t = (d == 0) ? -a * a : a * a;
    float lin = red512(t);
    float denom = sqrtf(fmaxf(-lin, 1e-8f));
    g_mean[d] = a / denom;
}

// ---------------------------------------------------------------------------
// 128-thread fused 3-way block reduce. Leading sync protects shared reuse and
// publishes any broadcast slots (sh[12..15]) written just before the call.
__device__ __forceinline__ void red3_128(float& a, float& b, float& c, float* sh) {
    __syncthreads();
    #pragma unroll
    for (int o = 16; o > 0; o >>= 1) {
        a += __shfl_down_sync(0xffffffffu, a, o);
        b += __shfl_down_sync(0xffffffffu, b, o);
        c += __shfl_down_sync(0xffffffffu, c, o);
    }
    int w = threadIdx.x >> 5;
    if ((threadIdx.x & 31) == 0) { sh[w] = a; sh[4 + w] = b; sh[8 + w] = c; }
    __syncthreads();
    a = sh[0] + sh[1] + sh[2] + sh[3];
    b = sh[4] + sh[5] + sh[6] + sh[7];
    c = sh[8] + sh[9] + sh[10] + sh[11];
}

// K2: main per-row pass
__global__ void __launch_bounds__(TPB) k_main(const float* __restrict__ x,
                                              const float* __restrict__ beta,
                                              const float* __restrict__ gamma,
                                              float* __restrict__ out) {
    __shared__ float sh[16];
    const int tid = threadIdx.x;
    const int base = tid * 4;
    const bool lead = (tid == 0);

    // per-thread mean/beta slice in registers
    float4 m4 = *(const float4*)(g_mean + base);
    float4 b4 = *(const float4*)(beta + base);
    float ms[4] = {m4.x, m4.y, m4.z, m4.w};
    float bs[4] = {b4.x, b4.y, b4.z, b4.w};
    const float g = gamma[0];

    // block-start constants: broadcast m0, beta0; Bc = <yo,yo>_L
    if (lead) { sh[14] = ms[0]; sh[15] = bs[0]; }
    float bsq = bs[0]*bs[0] + bs[1]*bs[1] + bs[2]*bs[2] + bs[3]*bs[3];
    if (lead) bsq -= bs[0]*bs[0];           // spatial-only
    float z1 = 0.f, z2 = 0.f;
    red3_128(bsq, z1, z2, sh);
    const float m0 = sh[14];
    const float b0 = sh[15];
    const float Bc = bsq - (1.f + b0) * (1.f + b0);   // -(1+b0)^2 + sum_{d>=1} b_d^2

    const size_t row0 = (size_t)blockIdx.x * RPB;

    for (int i = 0; i < RPB; i++) {
        const size_t r = row0 + i;
        const float4 xv = *(const float4*)(x + r * DD + base);
        float xs[4] = {xv.x, xv.y, xv.z, xv.w};

        // r1: Lorentz <mean,x>, sum(x), sum(x^2); broadcast x0
        float lin = 0.f, sum = 0.f, ss = 0.f;
        #pragma unroll
        for (int j = 0; j < 4; j++) {
            const float xx = xs[j];
            sum += xx;
            ss  += xx * xx;
            lin += ((lead && j == 0) ? -ms[0] * xx : ms[j] * xx);
        }
        if (lead) sh[12] = xs[0];
        red3_128(lin, sum, ss, sh);
        const float x0 = sh[12];

        const float alpha = fmaxf(-lin, 1.f + 1e-7f);
        const float dac   = acoshf(alpha);
        const float dnm   = sqrtf(alpha * alpha - 1.f);
        const float coef  = dac / dnm;

        const float var  = (ss - sum * sum * (1.f / DD)) * (1.f / (DD - 1));
        const float sfac = g * rsqrtf(var) + EPS_F;

        const float v0 = coef * (x0 - alpha * m0);
        const float tf = -v0 / (1.f + m0);

        // w = transp0back(logmap) * sfac ; r2: N = sum(w^2), L = <beta,w>_L
        float w[4];
        float N = 0.f, L = 0.f;
        #pragma unroll
        for (int j = 0; j < 4; j++) {
            const float vj = coef * (xs[j] - alpha * ms[j]);
            const float xo = ms[j] + ((lead && j == 0) ? 1.f : 0.f);
            const float wj = (vj + tf * xo) * sfac;
            w[j] = wj;
            N += wj * wj;
            L += ((lead && j == 0) ? -bs[0] * wj : bs[j] * wj);
        }
        if (lead) sh[13] = w[0];
        red3_128(N, L, z1, sh);
        const float w0 = sh[13];

        const float scale = fminf(1.f, MAXT * rsqrtf(fmaxf(N, 1e-8f)));
        const float f   = scale * L / (1.f + b0);
        const float wwL = N - 2.f * w0 * w0;
        const float wyo = L - w0;
        float n2 = scale * scale * wwL + 2.f * scale * f * wyo + f * f * Bc;
        n2 = fmaxf(n2, 1e-8f);
        const float n   = sqrtf(n2);
        const float chn = coshf(n);
        const float shn = sinhf(n) / n;

        float4 ov;
        float os[4];
        #pragma unroll
        for (int j = 0; j < 4; j++) {
            const float yo = bs[j] + ((lead && j == 0) ? 1.f : 0.f);
            const float uj = scale * w[j] + f * yo;
            os[j] = chn * bs[j] + shn * uj;
        }
        ov.x = os[0]; ov.y = os[1]; ov.z = os[2]; ov.w = os[3];
        *(float4*)(out + r * DD + base) = ov;
    }
}

// ---------------------------------------------------------------------------
extern "C" void kernel_launch(void* const* d_in, const int* in_sizes, int n_in,
                              void* d_out, int out_size) {
    const float* x = nullptr;
    const float* beta = nullptr;
    const float* gamma = nullptr;
    for (int i = 0; i < n_in; i++) {
        if (in_sizes[i] == BB * SS * DD)      x = (const float*)d_in[i];
        else if (in_sizes[i] == DD)           beta = (const float*)d_in[i];
        else if (in_sizes[i] == 1)            gamma = (const float*)d_in[i];
    }
    float* out = (float*)d_out;

    k_partial<<<BB * NCH, DD>>>(x);
    k_c1<<<BB, DD>>>();
    k_mean<<<1, DD>>>();
    k_main<<<NROWS / RPB, TPB>>>(x, beta, gamma, out);
}

// round 2
// speedup vs baseline: 1.6511x; 1.6511x over previous
#include <cuda_runtime.h>
#include <math.h>

#define BB 64
#define SS 1024
#define DD 512
#define NROWS (BB*SS)

#define NCH 16
#define SCHUNK (SS/NCH)

#define TPB 256
#define WPB (TPB/32)
#define RPW 4            // rows per warp

#define EPS_F 1e-5f
#define MAXT 45.054565f  // asinh(sqrt(fp32_max))
#define FULL 0xffffffffu

__device__ __align__(16) float g_part[BB*NCH*DD];
__device__ __align__(16) float g_c1[BB*DD];
__device__ __align__(16) float g_mean[DD];

// ---------------------------------------------------------------------------
__device__ __forceinline__ float red512(float v) {
    __shared__ float sh[16];
    int w = threadIdx.x >> 5, l = threadIdx.x & 31;
    #pragma unroll
    for (int o = 16; o > 0; o >>= 1) v += __shfl_down_sync(FULL, v, o);
    if (l == 0) sh[w] = v;
    __syncthreads();
    float r = 0.f;
    #pragma unroll
    for (int i = 0; i < 16; i++) r += sh[i];
    return r;
}

// K1a: per-(b,chunk) column partial sums over S, float4-vectorized
__global__ void __launch_bounds__(128) k_partial(const float* __restrict__ x) {
    int bc = blockIdx.x;            // b*NCH + c
    int t  = threadIdx.x;           // 0..127 -> float4 column t
    const float4* p = (const float4*)(x + (size_t)((bc / NCH) * SS + (bc % NCH) * SCHUNK) * DD) + t;
    float4 a0 = {0,0,0,0}, a1 = {0,0,0,0}, a2 = {0,0,0,0}, a3 = {0,0,0,0};
    #pragma unroll 4
    for (int s = 0; s < SCHUNK; s += 4) {
        float4 v0 = p[(size_t)(s + 0) * 128];
        float4 v1 = p[(size_t)(s + 1) * 128];
        float4 v2 = p[(size_t)(s + 2) * 128];
        float4 v3 = p[(size_t)(s + 3) * 128];
        a0.x += v0.x; a0.y += v0.y; a0.z += v0.z; a0.w += v0.w;
        a1.x += v1.x; a1.y += v1.y; a1.z += v1.z; a1.w += v1.w;
        a2.x += v2.x; a2.y += v2.y; a2.z += v2.z; a2.w += v2.w;
        a3.x += v3.x; a3.y += v3.y; a3.z += v3.z; a3.w += v3.w;
    }
    float4 r;
    r.x = (a0.x + a1.x) + (a2.x + a3.x);
    r.y = (a0.y + a1.y) + (a2.y + a3.y);
    r.z = (a0.z + a1.z) + (a2.z + a3.z);
    r.w = (a0.w + a1.w) + (a2.w + a3.w);
    ((float4*)(g_part + (size_t)bc * DD))[t] = r;
}

// K1b: per-b centroid normalization
__global__ void k_c1() {
    int b = blockIdx.x, d = threadIdx.x;
    float a = 0.f;
    #pragma unroll
    for (int c = 0; c < NCH; c++) a += g_part[(size_t)(b * NCH + c) * DD + d];
    a *= (1.f / SS);
    float t = (d == 0) ? -a * a : a * a;
    float lin = red512(t);
    float denom = sqrtf(fmaxf(-lin, 1e-8f));
    g_c1[(size_t)b * DD + d] = a / denom;
}

// K1c: centroid over B
__global__ void k_mean() {
    int d = threadIdx.x;
    float a = 0.f;
    #pragma unroll 8
    for (int b = 0; b < BB; b++) a += g_c1[(size_t)b * DD + d];
    a *= (1.f / BB);
    float t = (d == 0) ? -a * a : a * a;
    float lin = red512(t);
    float denom = sqrtf(fmaxf(-lin, 1e-8f));
    g_mean[d] = a / denom;
}

// ---------------------------------------------------------------------------
// K2: warp-per-row main pass, single 4-way butterfly reduction per row
__global__ void __launch_bounds__(TPB) k_main(const float* __restrict__ x,
                                              const float* __restrict__ beta,
                                              const float* __restrict__ gamma,
                                              float* __restrict__ out) {
    const int ln = threadIdx.x & 31;
    const int wp = threadIdx.x >> 5;

    // per-lane mean/beta slices: chunk k covers columns [k*128, k*128+128)
    float ms[16], bs[16];
    #pragma unroll
    for (int k = 0; k < 4; k++) {
        float4 m4 = *(const float4*)(g_mean + k * 128 + ln * 4);
        float4 b4 = *(const float4*)(beta   + k * 128 + ln * 4);
        ms[k*4+0] = m4.x; ms[k*4+1] = m4.y; ms[k*4+2] = m4.z; ms[k*4+3] = m4.w;
        bs[k*4+0] = b4.x; bs[k*4+1] = b4.y; bs[k*4+2] = b4.z; bs[k*4+3] = b4.w;
    }
    const float g = gamma[0];

    // prologue constants (per-warp, 3-way butterfly)
    float Mss = 0.f, Bme = 0.f, Bsq = 0.f;
    #pragma unroll
    for (int j = 0; j < 16; j++) {
        Mss = fmaf(ms[j], ms[j], Mss);
        Bme = fmaf(bs[j], ms[j], Bme);
        Bsq = fmaf(bs[j], bs[j], Bsq);
    }
    #pragma unroll
    for (int o = 16; o > 0; o >>= 1) {
        Mss += __shfl_xor_sync(FULL, Mss, o);
        Bme += __shfl_xor_sync(FULL, Bme, o);
        Bsq += __shfl_xor_sync(FULL, Bsq, o);
    }
    const float m0  = __shfl_sync(FULL, ms[0], 0);
    const float b0  = __shfl_sync(FULL, bs[0], 0);
    const float BmL = Bme - 2.f * b0 * m0;                       // <beta,mean>_L
    const float Bc  = (Bsq - b0 * b0) - (1.f + b0) * (1.f + b0); // <yo,yo>_L
    const float om0 = 1.f / (1.f + m0);
    const float ob0 = 1.f / (1.f + b0);
    const bool  lead = (ln == 0);

    const size_t row0 = ((size_t)blockIdx.x * WPB + wp) * RPW;

    for (int i = 0; i < RPW; i++) {
        const size_t r = row0 + i;
        const float4* px = (const float4*)(x + r * DD);

        float xs[16];
        #pragma unroll
        for (int k = 0; k < 4; k++) {
            float4 v = px[k * 32 + ln];
            xs[k*4+0] = v.x; xs[k*4+1] = v.y; xs[k*4+2] = v.z; xs[k*4+3] = v.w;
        }

        // fused 4-way row sums (all Euclidean)
        float sum = 0.f, ss = 0.f, exm = 0.f, exb = 0.f;
        #pragma unroll
        for (int j = 0; j < 16; j++) {
            const float xx = xs[j];
            sum += xx;
            ss  = fmaf(xx, xx, ss);
            exm = fmaf(xx, ms[j], exm);
            exb = fmaf(xx, bs[j], exb);
        }
        #pragma unroll
        for (int o = 16; o > 0; o >>= 1) {
            sum += __shfl_xor_sync(FULL, sum, o);
            ss  += __shfl_xor_sync(FULL, ss,  o);
            exm += __shfl_xor_sync(FULL, exm, o);
            exb += __shfl_xor_sync(FULL, exb, o);
        }
        const float x0 = __shfl_sync(FULL, xs[0], 0);

        const float lin  = exm - 2.f * x0 * m0;   // <mean,x>_L
        const float linb = exb - 2.f * x0 * b0;   // <beta,x>_L

        const float alpha = fmaxf(-lin, 1.f + 1e-7f);
        const float dnm   = sqrtf(alpha * alpha - 1.f);
        const float coef  = acoshf(alpha) / dnm;

        const float var  = (ss - sum * sum * (1.f / DD)) * (1.f / (DD - 1));
        const float sfac = g * rsqrtf(var) + EPS_F;

        const float v0 = coef * (x0 - alpha * m0);
        const float tf = -v0 * om0;
        const float A  = coef;
        const float C  = tf - coef * alpha;

        // N = sum(w^2), w0, L = <beta,w>_L -- all from scalar expansion
        const float N  = sfac * sfac * (A*A*ss + C*C*Mss + tf*tf
                        + 2.f*A*C*exm + 2.f*A*tf*x0 + 2.f*C*tf*m0);
        const float w0 = sfac * (A * x0 + C * m0 + tf);
        const float L  = sfac * (A * linb + C * BmL - tf * b0);

        const float scale = fminf(1.f, MAXT * rsqrtf(fmaxf(N, 1e-8f)));
        const float f = scale * L * ob0;

        float n2 = scale*scale*(N - 2.f*w0*w0) + 2.f*scale*f*(L - w0) + f*f*Bc;
        n2 = fmaxf(n2, 1e-8f);
        const float n   = sqrtf(n2);
        const float chn = coshf(n);
        const float shn = sinhf(n) / n;

        // out_j = c1*x_j + c2*m_j + c3*b_j (+ c4 on component 0)
        const float P  = scale * sfac * A;
        const float Q  = scale * sfac * C;
        const float c1 = shn * P;
        const float c2 = shn * Q;
        const float c3 = chn + shn * f;
        const float c4 = shn * (scale * sfac * tf + f);

        float4* po = (float4*)(out + r * DD);
        #pragma unroll
        for (int k = 0; k < 4; k++) {
            float4 ov;
            float o0 = fmaf(c1, xs[k*4+0], fmaf(c2, ms[k*4+0], c3 * bs[k*4+0]));
            float o1 = fmaf(c1, xs[k*4+1], fmaf(c2, ms[k*4+1], c3 * bs[k*4+1]));
            float o2 = fmaf(c1, xs[k*4+2], fmaf(c2, ms[k*4+2], c3 * bs[k*4+2]));
            float o3 = fmaf(c1, xs[k*4+3], fmaf(c2, ms[k*4+3], c3 * bs[k*4+3]));
            if (k == 0 && lead) o0 += c4;
            ov.x = o0; ov.y = o1; ov.z = o2; ov.w = o3;
            po[k * 32 + ln] = ov;
        }
    }
}

// ---------------------------------------------------------------------------
extern "C" void kernel_launch(void* const* d_in, const int* in_sizes, int n_in,
                              void* d_out, int out_size) {
    const float* x = nullptr;
    const float* beta = nullptr;
    const float* gamma = nullptr;
    for (int i = 0; i < n_in; i++) {
        if (in_sizes[i] == BB * SS * DD)      x = (const float*)d_in[i];
        else if (in_sizes[i] == DD)           beta = (const float*)d_in[i];
        else if (in_sizes[i] == 1)            gamma = (const float*)d_in[i];
    }
    float* out = (float*)d_out;

    k_partial<<<BB * NCH, 128>>>(x);
    k_c1<<<BB, DD>>>();
    k_mean<<<1, DD>>>();
    k_main<<<NROWS / (WPB * RPW), TPB>>>(x, beta, gamma, out);
}